// round 12
// baseline (speedup 1.0000x reference)
#include <cuda_runtime.h>
#include <cuda_fp16.h>
#include <cstdint>

#define NB 512
#define NR 196
#define DV 1024
#define DH 512
#define DA 256
#define KC 64                   // K elements per chunk
#define TPB 512                 // 16 warps: 4m x 4n grid, warp tile 16x64
#define AP 68                   // A smem pitch (fp32 floats)
#define MT 64                   // M tile rows per chunk
#define A_STAGE (MT * AP)       // 4352 floats
#define B_STAGE 8192            // u32: 32KB = two contiguous 16KB kc-slices of fp16 B
#define STG (A_STAGE + B_STAGE) // 12544 floats per stage (50.2KB)
#define NCH 64                  // 4 M-chunks x 16 K-chunks
#define SMEM_FLOATS (2 * STG + DA + DA + DA + 64 + 8)
#define SMEM_BYTES (SMEM_FLOATS * 4)

__device__ uint32_t g_Wvh[DV * DA / 2];   // fp16 Wv, B-fragment-major [kc32][ks2][wn][nf][lane][b0,b1]
__device__ float g_hproj[NB * DA];

// ---------------- helpers ----------------
static __device__ __forceinline__ uint32_t smem_u32(const void* p) {
    uint32_t a;
    asm("{ .reg .u64 t; cvta.to.shared.u64 t, %1; cvt.u32.u64 %0, t; }" : "=r"(a) : "l"(p));
    return a;
}
static __device__ __forceinline__ void cpa16(uint32_t dst, const void* src) {
    asm volatile("cp.async.cg.shared.global [%0], [%1], 16;" :: "r"(dst), "l"(src));
}
static __device__ __forceinline__ void cpa_commit() {
    asm volatile("cp.async.commit_group;" ::: "memory");
}
template <int N> static __device__ __forceinline__ void cpa_wait() {
    asm volatile("cp.async.wait_group %0;" :: "n"(N) : "memory");
}
static __device__ __forceinline__ void sts_zero16(uint32_t dst) {
    asm volatile("st.shared.v4.b32 [%0], {%1,%1,%1,%1};" :: "r"(dst), "r"(0) : "memory");
}
static __device__ __forceinline__ uint32_t pack_h2(float lo, float hi) {
    __half2 h = __floats2half2_rn(lo, hi);
    return *(uint32_t*)&h;
}
static __device__ __forceinline__ void mma16(float* c, const uint32_t* a, uint32_t b0, uint32_t b1) {
    asm volatile(
        "mma.sync.aligned.m16n8k16.row.col.f32.f16.f16.f32 "
        "{%0,%1,%2,%3}, {%4,%5,%6,%7}, {%8,%9}, {%0,%1,%2,%3};"
        : "+f"(c[0]), "+f"(c[1]), "+f"(c[2]), "+f"(c[3])
        : "r"(a[0]), "r"(a[1]), "r"(a[2]), "r"(a[3]), "r"(b0), "r"(b1));
}

// ---------------- setup: Wv->fp16 frag-major (blocks 0..511) + hproj (512..1023) ----------------
// u32 entry r = kc32*4096 + ks2*2048 + wn*512 + nf*64 + lane*2 + breg
__global__ __launch_bounds__(DA) void setup_kernel(
    const float* __restrict__ Wv,
    const float* __restrict__ hidden, const float* __restrict__ Wh,
    const float* __restrict__ bh)
{
    if (blockIdx.x < 512) {
        const int r = blockIdx.x * DA + threadIdx.x;
        const int breg = r & 1;
        const int lane = (r >> 1) & 31;
        const int nf   = (r >> 6) & 7;
        const int wn   = (r >> 9) & 3;
        const int ks2  = (r >> 11) & 1;
        const int kc   = r >> 12;
        const int col = wn * 64 + nf * 8 + (lane >> 2);
        const int k0  = kc * 32 + ks2 * 16 + 2 * (lane & 3) + breg * 8;
        g_Wvh[r] = pack_h2(Wv[k0 * DA + col], Wv[(k0 + 1) * DA + col]);
    } else {
        const int b = blockIdx.x - 512, a = threadIdx.x;
        const float* h = hidden + b * DH;
        const float* w = Wh + a;
        float acc = bh[a];
#pragma unroll 8
        for (int k = 0; k < DH; k++) acc = fmaf(h[k], w[k * DA], acc);
        g_hproj[b * DA + a] = acc;
    }
}

// ---------------- staging: A fp32 (2 cpa16/thr) + B fp16 double-slice (4 cpa16/thr) ----------------
static __device__ __forceinline__ void stage_chunk(int idx, uint32_t sS,
                                                   const float* __restrict__ vb, int t) {
    const int mc = idx >> 4, kc = idx & 15, buf = idx & 1;
    const int k0 = kc * KC;
    const uint32_t base = sS + (uint32_t)buf * (STG * 4);
#pragma unroll
    for (int i = 0; i < 2; i++) {                 // A: 64 rows x 16 segs of 16B
        int s = t + i * TPB;
        int row = s >> 4, seg = s & 15;
        int gr = mc * MT + row;
        uint32_t dst = base + row * (AP * 4) + seg * 16;
        if (gr < NR) cpa16(dst, vb + (size_t)gr * DV + k0 + seg * 4);
        else         sts_zero16(dst);
    }
    const uint32_t* bsrc = g_Wvh + (size_t)(2 * kc) * 4096;   // two contiguous 16KB slices
    const uint32_t bB = base + (uint32_t)(A_STAGE * 4);
#pragma unroll
    for (int i = 0; i < 4; i++) {
        int s = t + i * TPB;
        cpa16(bB + s * 16, bsrc + s * 4);
    }
}

// ---------------- fused: 1 CTA/batch, 512 thr, 2 CTAs/SM (32 warps), online softmax ----------------
__global__ __launch_bounds__(TPB, 2) void fused_kernel(
    const float* __restrict__ visual,
    const float* __restrict__ bv,
    const float* __restrict__ Wa,
    float* __restrict__ out)
{
    extern __shared__ float smem[];
    float* stg  = smem;                          // 2 * STG
    float* hpS  = smem + 2 * STG;
    float* waS  = hpS + DA;
    float* scS  = waS + DA;
    float* esS  = scS + DA;                      // 64 exp weights of current chunk
    float* misc = esS + 64;                      // [0]=max,[1]=den,[2]=scale

    const int b = blockIdx.x, t = threadIdx.x;
    const int wid = t >> 5, lane = t & 31, g = lane >> 2, tg = lane & 3;
    const int warp_m = wid >> 2, warp_n = wid & 3;    // 4x4 warps: warp tile 16 rows x 64 cols
    const float* vb = visual + (size_t)b * NR * DV;
    const float2* vb2 = (const float2*)vb;

    if (t < DA) {
        hpS[t] = g_hproj[b * DA + t] + bv[t];
        waS[t] = Wa[t];
        scS[t] = 0.0f;
    }
    if (t == 0) { misc[0] = -3.0e38f; misc[1] = 0.0f; misc[2] = 0.0f; }

    const uint32_t sS = smem_u32(stg);

    stage_chunk(0, sS, vb, t);
    cpa_commit();

    float acc[8][4];
#pragma unroll
    for (int nf = 0; nf < 8; nf++)
#pragma unroll
        for (int i = 0; i < 4; i++) acc[nf][i] = 0.0f;

    float2 num = make_float2(0.f, 0.f);          // output dims 2t, 2t+1

#pragma unroll 1
    for (int mc = 0; mc < 4; mc++) {
        // rows mc*64 + warp_m*16 .. +15; tail: only rows 192..207 (warp_m==0) matter
        const int active = (mc == 3) ? (warp_m == 0) : 1;

        for (int kc = 0; kc < 16; kc++) {
            const int idx = mc * 16 + kc;
            if (idx) __syncthreads();                  // WAR: restage target buffer drained
            if (idx + 1 < NCH) {
                stage_chunk(idx + 1, sS, vb, t);
                cpa_commit();
                cpa_wait<1>();                         // chunk idx landed (this thread)
            } else {
                cpa_wait<0>();
            }
            __syncthreads();                           // all threads' data landed

            if (active) {
                const int buf = idx & 1;
                const float* A = stg + buf * STG + (warp_m * 16) * AP;
                const uint2* Bw = (const uint2*)(stg + buf * STG + A_STAGE)
                                  + (warp_n * 8) * 32 + lane;     // [wn][nf][lane]
#pragma unroll
                for (int ks2 = 0; ks2 < 4; ks2++) {
                    const int kk = ks2 * 16 + 2 * tg;
                    uint32_t a[4];
                    {
                        const float* ar = A + g * AP + kk;
                        const float2 f0 = *(const float2*)(ar);
                        const float2 f1 = *(const float2*)(ar + 8 * AP);
                        const float2 f2 = *(const float2*)(ar + 8);
                        const float2 f3 = *(const float2*)(ar + 8 * AP + 8);
                        a[0] = pack_h2(f0.x, f0.y);
                        a[1] = pack_h2(f1.x, f1.y);
                        a[2] = pack_h2(f2.x, f2.y);
                        a[3] = pack_h2(f3.x, f3.y);
                    }
                    const uint2* Bk = Bw + ks2 * 1024;    // ks2 stride = 4*8*32 uint2
#pragma unroll
                    for (int nf = 0; nf < 8; nf++) {
                        const uint2 bb = Bk[nf * 32];
                        mma16(acc[nf], a, bb.x, bb.y);
                    }
                }
            }
        }

        // ---- score epilogue: relu(c+hp)*wa, partial over this warp's 64 cols -> scS ----
        if (active) {
            float pA = 0.0f, pB = 0.0f;
#pragma unroll
            for (int nf = 0; nf < 8; nf++) {
                const int col = warp_n * 64 + nf * 8 + 2 * tg;
                const float hp0 = hpS[col], hp1 = hpS[col + 1];
                const float wa0 = waS[col], wa1 = waS[col + 1];
                pA += fmaxf(acc[nf][0] + hp0, 0.0f) * wa0
                    + fmaxf(acc[nf][1] + hp1, 0.0f) * wa1;
                pB += fmaxf(acc[nf][2] + hp0, 0.0f) * wa0
                    + fmaxf(acc[nf][3] + hp1, 0.0f) * wa1;
#pragma unroll
                for (int i = 0; i < 4; i++) acc[nf][i] = 0.0f;
            }
            pA += __shfl_xor_sync(0xffffffffu, pA, 1);
            pA += __shfl_xor_sync(0xffffffffu, pA, 2);
            pB += __shfl_xor_sync(0xffffffffu, pB, 1);
            pB += __shfl_xor_sync(0xffffffffu, pB, 2);
            if (tg == 0) {
                const int r0 = mc * MT + warp_m * 16 + g;
                atomicAdd(&scS[r0],     pA);
                atomicAdd(&scS[r0 + 8], pB);
            }
        }
        __syncthreads();       // scores of this chunk final

        // ---- online softmax state update (warp 0) ----
        if (wid == 0) {
            const int r0 = mc * MT;
            float s0 = (r0 + lane      < NR) ? scS[r0 + lane]      : -3.0e38f;
            float s1 = (r0 + 32 + lane < NR) ? scS[r0 + 32 + lane] : -3.0e38f;
            float mx = fmaxf(s0, s1);
#pragma unroll
            for (int off = 16; off; off >>= 1)
                mx = fmaxf(mx, __shfl_xor_sync(0xffffffffu, mx, off));
            const float Mold = misc[0];
            const float Mnew = fmaxf(Mold, mx);
            const float scl  = __expf(Mold - Mnew);
            const float e0 = __expf(s0 - Mnew);
            const float e1 = __expf(s1 - Mnew);
            esS[lane]      = e0;
            esS[32 + lane] = e1;
            float se = e0 + e1;
#pragma unroll
            for (int off = 16; off; off >>= 1)
                se += __shfl_xor_sync(0xffffffffu, se, off);
            if (lane == 0) {
                misc[1] = misc[1] * scl + se;
                misc[0] = Mnew;
                misc[2] = scl;
            }
        }
        __syncthreads();

        // ---- numerator accumulation from L2-hot rows of this chunk (float2/thread) ----
        {
            const float scl = misc[2];
            const int nrr = (mc < 3) ? MT : (NR - 3 * MT);   // 64 or 4
            float2 s = make_float2(0.f, 0.f);
            for (int rr = 0; rr < nrr; rr++) {
                const float e = esS[rr];
                const float2 x = vb2[(size_t)(mc * MT + rr) * (DV / 2) + t];
                s.x = fmaf(e, x.x, s.x);
                s.y = fmaf(e, x.y, s.y);
            }
            num.x = fmaf(num.x, scl, s.x);
            num.y = fmaf(num.y, scl, s.y);
        }
        __syncthreads();       // esS/misc stable before next chunk's epilogue
    }

    const float inv = 1.0f / misc[1];
    num.x *= inv; num.y *= inv;
    ((float2*)out)[(size_t)b * (DV / 2) + t] = num;
}

extern "C" void kernel_launch(void* const* d_in, const int* in_sizes, int n_in,
                              void* d_out, int out_size) {
    const float* visual = (const float*)d_in[0];
    const float* hidden = (const float*)d_in[1];
    const float* Wv     = (const float*)d_in[2];
    const float* bv     = (const float*)d_in[3];
    const float* Wh     = (const float*)d_in[4];
    const float* bh     = (const float*)d_in[5];
    const float* Wa     = (const float*)d_in[6];
    // d_in[7] = ba: additive constant over regions -> softmax-invariant, intentionally unused
    float* out = (float*)d_out;
    (void)in_sizes; (void)n_in; (void)out_size;

    cudaFuncSetAttribute(fused_kernel, cudaFuncAttributeMaxDynamicSharedMemorySize, SMEM_BYTES);

    setup_kernel<<<1024, DA>>>(Wv, hidden, Wh, bh);
    fused_kernel<<<NB, TPB, SMEM_BYTES>>>(visual, bv, Wa, out);
}